// round 1
// baseline (speedup 1.0000x reference)
#include <cuda_runtime.h>
#include <cuda_bf16.h>

// Problem constants
#define C_IN   256
#define C_OUT  256
#define HW     56
#define HWSQ   (HW * HW)          // 3136
#define KTAPS  9
#define KELEM  (C_IN * KTAPS)     // 2304 per output channel

// Scratch: quantized+scaled weights, [oc][ic][kh*3+kw], fp32.
__device__ float g_wq[(size_t)C_OUT * KELEM];

// ---------------------------------------------------------------------------
// Kernel A: ternary quantization. One block per output channel.
// delta = 0.7 * mean(|w|); ternary = sign-threshold; alpha = mean(|w| over
// nonzero taps); writes alpha*ternary.
// ---------------------------------------------------------------------------
__global__ void quant_kernel(const float* __restrict__ w) {
    const int oc  = blockIdx.x;
    const int tid = threadIdx.x;
    const float* wo = w + (size_t)oc * KELEM;
    __shared__ float red[256];

    // Pass 1: sum |w|
    float s = 0.f;
    for (int i = tid; i < KELEM; i += 256) s += fabsf(wo[i]);
    red[tid] = s;
    __syncthreads();
    #pragma unroll
    for (int st = 128; st > 0; st >>= 1) {
        if (tid < st) red[tid] += red[tid + st];
        __syncthreads();
    }
    const float delta = 0.7f * red[0] / (float)KELEM;
    __syncthreads();

    // Pass 2: masked sum + count
    float ms = 0.f, cnt = 0.f;
    for (int i = tid; i < KELEM; i += 256) {
        float a = fabsf(wo[i]);
        if (a > delta) { ms += a; cnt += 1.f; }
    }
    red[tid] = ms;
    __syncthreads();
    #pragma unroll
    for (int st = 128; st > 0; st >>= 1) {
        if (tid < st) red[tid] += red[tid + st];
        __syncthreads();
    }
    const float mtot = red[0];
    __syncthreads();
    red[tid] = cnt;
    __syncthreads();
    #pragma unroll
    for (int st = 128; st > 0; st >>= 1) {
        if (tid < st) red[tid] += red[tid + st];
        __syncthreads();
    }
    const float ctot = red[0];
    const float alpha = mtot / fmaxf(ctot, 1.f);

    // Pass 3: write scaled ternary weights
    float* dst = g_wq + (size_t)oc * KELEM;
    for (int i = tid; i < KELEM; i += 256) {
        float v = wo[i];
        dst[i] = (v > delta) ? alpha : ((v < -delta) ? -alpha : 0.f);
    }
}

// ---------------------------------------------------------------------------
// Kernel B: direct 3x3 conv, stride 1, pad 1, fp32.
// Tile per CTA: 64 output channels x (8 x 8) output pixels, one n.
// IC chunked by 8. Thread register tile: 4 oc x 4 contiguous ow pixels.
// Thread map (256 threads): pxg = tid & 15  -> (row r = pxg>>1, colgroup cg = pxg&1)
//                           ocg = tid >> 4  -> local oc base = ocg*4
// ---------------------------------------------------------------------------
#define ICC     8
#define TOC     64
#define TILE_H  8
#define TILE_W  8

__global__ __launch_bounds__(256) void conv_kernel(
    const float* __restrict__ x, float* __restrict__ out)
{
    __shared__ float sIn[ICC][10][12];       // rows 10, cols 0..9 used
    __shared__ float sW[TOC][ICC][12];       // 9 taps used, padded to 12 for f4 align

    const int tid = threadIdx.x;
    const int pxg = tid & 15;
    const int ocg = tid >> 4;
    const int r   = pxg >> 1;        // 0..7 tile row
    const int cg  = pxg & 1;         // 0..1 -> ow base 4*cg
    const int ocl = ocg * 4;         // local oc base 0..60

    const int n    = blockIdx.z;
    const int oc0  = blockIdx.y * TOC;
    const int tile = blockIdx.x;     // 0..48
    const int oh0  = (tile / 7) * TILE_H;
    const int ow0  = (tile % 7) * TILE_W;

    const float* xn = x + (size_t)n * C_IN * HWSQ;

    float acc[4][4];
    #pragma unroll
    for (int o = 0; o < 4; o++)
        #pragma unroll
        for (int p = 0; p < 4; p++) acc[o][p] = 0.f;

    for (int ic0 = 0; ic0 < C_IN; ic0 += ICC) {
        __syncthreads();
        // ---- load input halo tile: ICC x 10 x 10 ----
        for (int idx = tid; idx < ICC * 100; idx += 256) {
            int ic = idx / 100;
            int rem = idx - ic * 100;
            int rr = rem / 10;
            int cc = rem - rr * 10;
            int ih = oh0 - 1 + rr;
            int iw = ow0 - 1 + cc;
            float v = 0.f;
            if ((unsigned)ih < (unsigned)HW && (unsigned)iw < (unsigned)HW)
                v = xn[(size_t)(ic0 + ic) * HWSQ + ih * HW + iw];
            sIn[ic][rr][cc] = v;
        }
        // ---- load weight tile: TOC x ICC x 9 ----
        for (int idx = tid; idx < TOC * ICC * KTAPS; idx += 256) {
            int oc = idx / (ICC * KTAPS);
            int rem = idx - oc * (ICC * KTAPS);
            int ic = rem / KTAPS;
            int k  = rem - ic * KTAPS;
            sW[oc][ic][k] = g_wq[(size_t)(oc0 + oc) * KELEM + (ic0 + ic) * KTAPS + k];
        }
        __syncthreads();

        // ---- compute ----
        #pragma unroll
        for (int ic = 0; ic < ICC; ic++) {
            float xin[3][6];
            #pragma unroll
            for (int kh = 0; kh < 3; kh++) {
                const float* row = &sIn[ic][r + kh][4 * cg];
                float4 a = *(const float4*)row;
                float2 b = *(const float2*)(row + 4);
                xin[kh][0] = a.x; xin[kh][1] = a.y; xin[kh][2] = a.z; xin[kh][3] = a.w;
                xin[kh][4] = b.x; xin[kh][5] = b.y;
            }
            #pragma unroll
            for (int o = 0; o < 4; o++) {
                const float* wp = sW[ocl + o][ic];
                float4 w0 = *(const float4*)wp;
                float4 w1 = *(const float4*)(wp + 4);
                float  w8 = wp[8];
                float wv[9];
                wv[0] = w0.x; wv[1] = w0.y; wv[2] = w0.z; wv[3] = w0.w;
                wv[4] = w1.x; wv[5] = w1.y; wv[6] = w1.z; wv[7] = w1.w;
                wv[8] = w8;
                #pragma unroll
                for (int kh = 0; kh < 3; kh++) {
                    #pragma unroll
                    for (int kw = 0; kw < 3; kw++) {
                        float wr = wv[kh * 3 + kw];
                        #pragma unroll
                        for (int p = 0; p < 4; p++)
                            acc[o][p] += wr * xin[kh][kw + p];
                    }
                }
            }
        }
    }

    // ---- epilogue ----
    const int oh = oh0 + r;
    const int owb = ow0 + 4 * cg;
    #pragma unroll
    for (int o = 0; o < 4; o++) {
        const int oc = oc0 + ocl + o;
        float* dst = out + ((size_t)(n * C_OUT + oc)) * HWSQ + oh * HW + owb;
        #pragma unroll
        for (int p = 0; p < 4; p++) dst[p] = acc[o][p];
    }
}

// ---------------------------------------------------------------------------
extern "C" void kernel_launch(void* const* d_in, const int* in_sizes, int n_in,
                              void* d_out, int out_size) {
    const float* x = (const float*)d_in[0];
    const float* w = (const float*)d_in[1];
    float* out = (float*)d_out;

    quant_kernel<<<C_OUT, 256>>>(w);

    dim3 grid(49, C_OUT / TOC, 32);   // spatial tiles, oc tiles, batch
    conv_kernel<<<grid, 256>>>(x, out);

    (void)in_sizes; (void)n_in; (void)out_size;
}